// round 2
// baseline (speedup 1.0000x reference)
#include <cuda_runtime.h>
#include <cuda_bf16.h>
#include <math.h>

// Problem constants
#define V_    50000
#define IN_   300
#define M_    150
#define G3_   450      // 3*M
#define NL_   200000
#define D_    6
#define N_    40000
#define K_    4
#define B_    64
#define S_    64
#define NCTX  (B_*S_)          // 4096
#define NJOB  (NCTX*5)         // 20480: slot e*5+0 = direct leaf, e*5+1..4 = children

#define TB 8   // leaf jobs per block
#define TC 8   // ctx elements per dep block

// Scratch (device globals — no allocation allowed)
__device__ int   g_job[NJOB];          // leaf index (0..NL-1) or -1
__device__ int   g_type[NCTX];         // 0=zero slot, 1=leaf, 2=dep
__device__ int   g_word[NCTX];         // word idx for dep elements
__device__ float g_c[(size_t)NJOB * M_];
__device__ float g_h[(size_t)NJOB * M_];

__device__ __forceinline__ float sigm(float x) { return 1.0f / (1.0f + expf(-x)); }

// ---------------------------------------------------------------------------
// Kernel A: classify each ctx element, build the leaf-job list
// ---------------------------------------------------------------------------
__global__ void build_jobs_kernel(const int* __restrict__ ctx,
                                  const int* __restrict__ dep_word,
                                  const int* __restrict__ dep_child) {
    int e = blockIdx.x * blockDim.x + threadIdx.x;
    if (e >= NCTX) return;
    int s = ctx[e];
    int base = e * 5;
    int j[5] = {-1, -1, -1, -1, -1};
    int type = 0, word = 0;
    if (s == 0) {
        type = 0;
    } else if (s <= NL_) {
        type = 1;
        j[0] = s - 1;
    } else {
        type = 2;
        int node = s - 1 - NL_;          // 0 .. D*N-1 (layer-major, matches [D,N] flat)
        word = dep_word[node];
        #pragma unroll
        for (int k = 0; k < K_; k++) {
            int cs = dep_child[node * K_ + k];   // slot in [1, 1+NL)
            j[1 + k] = (cs >= 1 && cs <= NL_) ? (cs - 1) : -1;
        }
    }
    #pragma unroll
    for (int q = 0; q < 5; q++) g_job[base + q] = j[q];
    g_type[e] = type;
    g_word[e] = word;
}

// ---------------------------------------------------------------------------
// Kernel B: leaf cell for every job slot.
// Block handles TB=8 jobs; 150 compute threads, one per M-lane, 3 gates each.
// W_leaf columns are read once per block (L2-resident), x rows live in SMEM.
// ---------------------------------------------------------------------------
__global__ void __launch_bounds__(160, 4)
leaf_kernel(const float* __restrict__ embed,
            const float* __restrict__ Wl,
            const float* __restrict__ bl,
            const int*   __restrict__ leaf_idx) {
    __shared__ float sx[TB * IN_];     // 9600 floats
    __shared__ int   sjob[TB];
    __shared__ int   sword[TB];

    const int jb  = blockIdx.x * TB;
    const int tid = threadIdx.x;

    if (tid < TB) {
        int j = g_job[jb + tid];
        sjob[tid]  = j;
        sword[tid] = (j >= 0) ? leaf_idx[j] : -1;
    }
    __syncthreads();

    // gather embedding rows (zeros for inactive jobs)
    for (int idx = tid; idx < TB * IN_; idx += blockDim.x) {
        int l = idx / IN_;
        int t = idx - l * IN_;
        int w = sword[l];
        sx[idx] = (w >= 0) ? embed[(size_t)w * IN_ + t] : 0.0f;
    }
    __syncthreads();

    if (tid < M_) {
        float ai[TB], ao[TB], au[TB];
        #pragma unroll
        for (int l = 0; l < TB; l++) { ai[l] = 0.f; ao[l] = 0.f; au[l] = 0.f; }

        #pragma unroll 2
        for (int t = 0; t < IN_; t++) {
            float w0 = __ldg(Wl + (size_t)t * G3_ + tid);
            float w1 = __ldg(Wl + (size_t)t * G3_ + M_ + tid);
            float w2 = __ldg(Wl + (size_t)t * G3_ + 2 * M_ + tid);
            #pragma unroll
            for (int l = 0; l < TB; l++) {
                float xv = sx[l * IN_ + t];
                ai[l] = fmaf(xv, w0, ai[l]);
                ao[l] = fmaf(xv, w1, ao[l]);
                au[l] = fmaf(xv, w2, au[l]);
            }
        }
        const float bi = bl[tid], bo = bl[M_ + tid], bu = bl[2 * M_ + tid];
        #pragma unroll
        for (int l = 0; l < TB; l++) {
            float* pc = g_c + (size_t)(jb + l) * M_ + tid;
            float* ph = g_h + (size_t)(jb + l) * M_ + tid;
            if (sjob[l] < 0) {
                *pc = 0.0f; *ph = 0.0f;
            } else {
                float i_ = sigm(ai[l] + bi);
                float o_ = sigm(ao[l] + bo);
                float u_ = tanhf(au[l] + bu);
                float c  = i_ * u_;
                float h  = o_ * tanhf(c);
                *pc = c; *ph = h;
            }
        }
    }
}

// ---------------------------------------------------------------------------
// Kernel C: dep-node cell for ctx elements of type 2.
// Block handles TC=8 ctx elements; 150 compute threads (one per M-lane).
// ---------------------------------------------------------------------------
__global__ void __launch_bounds__(160, 2)
dep_kernel(const float* __restrict__ embed,
           const float* __restrict__ Wiou,
           const float* __restrict__ Uiou,
           const float* __restrict__ biou,
           const float* __restrict__ Wf,
           const float* __restrict__ Uf,
           const float* __restrict__ bf,
           float* __restrict__ out) {
    __shared__ float sxd[TC * IN_];          // 9600 floats
    __shared__ float sh [TC * K_ * M_];      // 4800 floats
    __shared__ float shs[TC * M_];           // 1200 floats
    __shared__ int   styp[TC];
    __shared__ int   sword[TC];

    const int eb  = blockIdx.x * TC;
    const int tid = threadIdx.x;

    if (tid < TC) {
        styp[tid]  = g_type[eb + tid];
        sword[tid] = g_word[eb + tid];
    }
    __syncthreads();

    // load word embeddings
    for (int idx = tid; idx < TC * IN_; idx += blockDim.x) {
        int l = idx / IN_;
        int t = idx - l * IN_;
        sxd[idx] = (styp[l] == 2) ? embed[(size_t)sword[l] * IN_ + t] : 0.0f;
    }
    // load child h states
    for (int idx = tid; idx < TC * K_ * M_; idx += blockDim.x) {
        int l = idx / (K_ * M_);
        int r = idx - l * (K_ * M_);
        int k = r / M_;
        int t = r - k * M_;
        sh[idx] = (styp[l] == 2) ? g_h[((size_t)(eb + l) * 5 + 1 + k) * M_ + t] : 0.0f;
    }
    __syncthreads();
    // child-sum
    for (int idx = tid; idx < TC * M_; idx += blockDim.x) {
        int l = idx / M_;
        int t = idx - l * M_;
        shs[idx] = sh[(l * K_ + 0) * M_ + t] + sh[(l * K_ + 1) * M_ + t]
                 + sh[(l * K_ + 2) * M_ + t] + sh[(l * K_ + 3) * M_ + t];
    }
    __syncthreads();

    if (tid < M_) {
        float ai[TC], ao[TC], au[TC], axf[TC];
        float af[TC][K_];
        #pragma unroll
        for (int l = 0; l < TC; l++) {
            ai[l] = 0.f; ao[l] = 0.f; au[l] = 0.f; axf[l] = 0.f;
            #pragma unroll
            for (int k = 0; k < K_; k++) af[l][k] = 0.f;
        }

        // x-side: xd @ W_iou (3 gates) and xd @ W_f
        for (int t = 0; t < IN_; t++) {
            float wi = __ldg(Wiou + (size_t)t * G3_ + tid);
            float wo = __ldg(Wiou + (size_t)t * G3_ + M_ + tid);
            float wu = __ldg(Wiou + (size_t)t * G3_ + 2 * M_ + tid);
            float wf = __ldg(Wf   + (size_t)t * M_ + tid);
            #pragma unroll
            for (int l = 0; l < TC; l++) {
                float xv = sxd[l * IN_ + t];
                ai[l]  = fmaf(xv, wi, ai[l]);
                ao[l]  = fmaf(xv, wo, ao[l]);
                au[l]  = fmaf(xv, wu, au[l]);
                axf[l] = fmaf(xv, wf, axf[l]);
            }
        }
        // h-side: h_sum @ U_iou and per-child h_k @ U_f
        for (int t = 0; t < M_; t++) {
            float ui = __ldg(Uiou + (size_t)t * G3_ + tid);
            float uo = __ldg(Uiou + (size_t)t * G3_ + M_ + tid);
            float uu = __ldg(Uiou + (size_t)t * G3_ + 2 * M_ + tid);
            float uf = __ldg(Uf   + (size_t)t * M_ + tid);
            #pragma unroll
            for (int l = 0; l < TC; l++) {
                float hv = shs[l * M_ + t];
                ai[l] = fmaf(hv, ui, ai[l]);
                ao[l] = fmaf(hv, uo, ao[l]);
                au[l] = fmaf(hv, uu, au[l]);
                #pragma unroll
                for (int k = 0; k < K_; k++)
                    af[l][k] = fmaf(sh[(l * K_ + k) * M_ + t], uf, af[l][k]);
            }
        }

        const float bi = biou[tid], bo = biou[M_ + tid], bu = biou[2 * M_ + tid];
        const float bff = bf[tid];
        #pragma unroll
        for (int l = 0; l < TC; l++) {
            if (styp[l] != 2) continue;
            int e = eb + l;
            float i_ = sigm(ai[l] + bi);
            float o_ = sigm(ao[l] + bo);
            float u_ = tanhf(au[l] + bu);
            float c  = i_ * u_;
            #pragma unroll
            for (int k = 0; k < K_; k++) {
                float f  = sigm(axf[l] + af[l][k] + bff);
                float cc = g_c[((size_t)e * 5 + 1 + k) * M_ + tid];
                c = fmaf(f, cc, c);
            }
            float h = o_ * tanhf(c);
            out[(size_t)e * M_ + tid] = c;                          // c half
            out[(size_t)NCTX * M_ + (size_t)e * M_ + tid] = h;      // h half
        }
    }
}

// ---------------------------------------------------------------------------
// Kernel D: leaf-type and zero-type ctx elements (dep handled by kernel C)
// ---------------------------------------------------------------------------
__global__ void finish_kernel(float* __restrict__ out) {
    int idx = blockIdx.x * blockDim.x + threadIdx.x;   // over NCTX*M
    if (idx >= NCTX * M_) return;
    int e = idx / M_;
    int m = idx - e * M_;
    int t = g_type[e];
    if (t == 2) return;
    float c = 0.f, h = 0.f;
    if (t == 1) {
        c = g_c[(size_t)e * 5 * M_ + m];
        h = g_h[(size_t)e * 5 * M_ + m];
    }
    out[idx] = c;
    out[(size_t)NCTX * M_ + idx] = h;
}

// ---------------------------------------------------------------------------
extern "C" void kernel_launch(void* const* d_in, const int* in_sizes, int n_in,
                              void* d_out, int out_size) {
    const float* embed     = (const float*)d_in[0];
    const float* W_leaf    = (const float*)d_in[1];
    const float* b_leaf    = (const float*)d_in[2];
    const float* W_iou     = (const float*)d_in[3];
    const float* U_iou     = (const float*)d_in[4];
    const float* b_iou     = (const float*)d_in[5];
    const float* W_f       = (const float*)d_in[6];
    const float* U_f       = (const float*)d_in[7];
    const float* b_f       = (const float*)d_in[8];
    const int*   leaf_idx  = (const int*)d_in[9];
    const int*   dep_word  = (const int*)d_in[10];
    const int*   dep_child = (const int*)d_in[11];
    const int*   ctx_idx   = (const int*)d_in[12];
    float* out = (float*)d_out;

    build_jobs_kernel<<<(NCTX + 255) / 256, 256>>>(ctx_idx, dep_word, dep_child);
    leaf_kernel<<<NJOB / TB, 160>>>(embed, W_leaf, b_leaf, leaf_idx);
    dep_kernel<<<NCTX / TC, 160>>>(embed, W_iou, U_iou, b_iou, W_f, U_f, b_f, out);
    finish_kernel<<<(NCTX * M_ + 255) / 256, 256>>>(out);
}